// round 14
// baseline (speedup 1.0000x reference)
#include <cuda_runtime.h>
#include <cuda_fp16.h>
#include <stdint.h>

// Problem constants
#define NN 8192
#define MM 8192
#define DD 64
#define TILE 128
#define NTILE (NN / TILE)   // 64

// ---------------- device scratch (no allocations allowed) ----------------
// fp16 2-way splits, each row = 64 halfs = 128B = 8 uint4
__device__ uint4 g_xh[NN * 8];
__device__ uint4 g_xl[NN * 8];
__device__ uint4 g_yh[NN * 8];
__device__ uint4 g_yl[NN * 8];

__device__ float g_xsq[NN];
__device__ float g_ysq[MM];
__device__ float g_rowsum[NN];
__device__ float g_colsum[MM];
__device__ unsigned long long g_rowmaxp[NN];
__device__ unsigned long long g_colmaxp[MM];
__device__ float g_lp_rows[NN];
__device__ float g_lp_cols[MM];
__device__ int   g_choice_rows[NN];
__device__ int   g_choice_cols[MM];

// ---------------- helpers ----------------
__device__ __forceinline__ unsigned fkey(float f) {
    unsigned u = __float_as_uint(f);
    return u ^ ((unsigned)(((int)u) >> 31) | 0x80000000u);
}
__device__ __forceinline__ float unfkey(unsigned k) {
    unsigned u = (k & 0x80000000u) ? (k ^ 0x80000000u) : ~k;
    return __uint_as_float(u);
}
__device__ __forceinline__ uint32_t smem_u32(const void* p) {
    uint32_t a;
    asm("{ .reg .u64 t; cvta.to.shared.u64 t, %1; cvt.u32.u64 %0, t; }"
        : "=r"(a) : "l"(p));
    return a;
}
__device__ __forceinline__ void ldsm4(uint32_t& r0, uint32_t& r1, uint32_t& r2,
                                      uint32_t& r3, uint32_t addr) {
    asm volatile("ldmatrix.sync.aligned.m8n8.x4.shared.b16 {%0,%1,%2,%3}, [%4];"
                 : "=r"(r0), "=r"(r1), "=r"(r2), "=r"(r3) : "r"(addr));
}
__device__ __forceinline__ void mma_f16(float& d0, float& d1, float& d2, float& d3,
                                        uint32_t a0, uint32_t a1, uint32_t a2, uint32_t a3,
                                        uint32_t b0, uint32_t b1) {
    asm("mma.sync.aligned.m16n8k16.row.col.f32.f16.f16.f32 "
        "{%0,%1,%2,%3}, {%4,%5,%6,%7}, {%8,%9}, {%0,%1,%2,%3};"
        : "+f"(d0), "+f"(d1), "+f"(d2), "+f"(d3)
        : "r"(a0), "r"(a1), "r"(a2), "r"(a3), "r"(b0), "r"(b1));
}

// ---------------- prep: zero accums, sqnorms, fp16 2-way split ----------------
__global__ void prep_kernel(const float* __restrict__ x, const float* __restrict__ y) {
    int t = blockIdx.x * blockDim.x + threadIdx.x;
    if (t < NN) {
        g_rowsum[t] = 0.f; g_colsum[t] = 0.f;
        g_rowmaxp[t] = 0ull; g_colmaxp[t] = 0ull;
    }
    if (t >= 2 * NN) return;
    int r = (t < NN) ? t : (t - NN);
    const float* src = (t < NN) ? (x + (size_t)r * DD) : (y + (size_t)r * DD);
    __half2* ph = ((t < NN) ? (__half2*)g_xh : (__half2*)g_yh) + (size_t)r * 32;
    __half2* pl = ((t < NN) ? (__half2*)g_xl : (__half2*)g_yl) + (size_t)r * 32;

    float s = 0.f;
#pragma unroll
    for (int k = 0; k < 32; ++k) {
        float2 v = ((const float2*)src)[k];
        s += v.x * v.x + v.y * v.y;
        __half ha = __float2half(v.x);
        __half la = __float2half(v.x - __half2float(ha));
        __half hb = __float2half(v.y);
        __half lb = __float2half(v.y - __half2float(hb));
        __half2 vh; vh.x = ha; vh.y = hb;
        __half2 vl; vl.x = la; vl.y = lb;
        ph[k] = vh; pl[k] = vl;
    }
    if (t < NN) g_xsq[r] = s; else g_ysq[r] = s;
}

// ---------------- smem layout: 4 tiles (xh xl yh yl), 128 rows x 128B, SW128 ----------------
#define H_SXQ  (4 * 16384)            // 65536
#define H_SYQ  (H_SXQ + 512)
#define H_CSUM (H_SYQ + 512)
#define H_RSUM (H_CSUM + 512)
#define H_CMAX (H_RSUM + 512)
#define H_RMAX (H_CMAX + 1024)
#define SMEM_TOTAL (H_RMAX + 1024)    // 69632

// ---------------- main: fp16 2-way split, 3-term mma.sync + fused stats ----------------
__global__ void __launch_bounds__(256, 2)
matcher_main_kernel() {
    extern __shared__ char smem[];
    uint32_t sbase = smem_u32(smem);
    const int tid = threadIdx.x;
    const int w = tid >> 5;
    const int lane = tid & 31;
    const int ibase = blockIdx.y * TILE;
    const int jbase = blockIdx.x * TILE;

    float* s_sxq = (float*)(smem + H_SXQ);
    float* s_syq = (float*)(smem + H_SYQ);
    float* s_csum = (float*)(smem + H_CSUM);
    float* s_rsum = (float*)(smem + H_RSUM);
    unsigned long long* s_cmax = (unsigned long long*)(smem + H_CMAX);
    unsigned long long* s_rmax = (unsigned long long*)(smem + H_RMAX);

    // load 4 fp16 tiles with SW128 swizzle (128B rows)
#pragma unroll
    for (int t4 = 0; t4 < 4; ++t4) {
        const uint4* src = (t4 == 0) ? g_xh : (t4 == 1) ? g_xl
                         : (t4 == 2) ? g_yh : g_yl;
        int rbase = (t4 < 2) ? ibase : jbase;
        char* dst = smem + t4 * 16384;
        for (int k = tid; k < 1024; k += 256) {
            int row = k >> 3;
            int c = k & 7;
            uint4 v = src[(size_t)(rbase + row) * 8 + c];
            uint32_t bo = (uint32_t)(row * 128 + c * 16);
            *(uint4*)(dst + (bo ^ ((bo >> 3) & 0x70))) = v;
        }
    }
    if (tid < 128) {
        s_sxq[tid] = g_xsq[ibase + tid];
        s_syq[tid] = g_ysq[jbase + tid];
        s_csum[tid] = 0.f; s_rsum[tid] = 0.f;
        s_cmax[tid] = 0ull; s_rmax[tid] = 0ull;
    }
    __syncthreads();

    // warp partition: rows mblk..mblk+31 (2 m16 tiles), cols nblk..nblk+63 (8 n8 tiles)
    const int mblk = (w & 3) * 32;
    const int nblk = (w >> 2) * 64;
    const int mi = lane >> 3;
    const int l7 = lane & 7;

    uint32_t a_pre[2], b_pre[4];
#pragma unroll
    for (int mt = 0; mt < 2; ++mt)
        a_pre[mt] = (uint32_t)((mblk + mt * 16 + (mi & 1) * 8 + l7) * 128 + (mi >> 1) * 16);
#pragma unroll
    for (int p4 = 0; p4 < 4; ++p4)
        b_pre[p4] = (uint32_t)((nblk + p4 * 16 + (mi >> 1) * 8 + l7) * 128 + (mi & 1) * 16);

    float acc[2][8][4];
#pragma unroll
    for (int mt = 0; mt < 2; ++mt)
#pragma unroll
        for (int nt = 0; nt < 8; ++nt)
#pragma unroll
            for (int k = 0; k < 4; ++k) acc[mt][nt][k] = 0.f;

    // 3 terms: hh + lh (B=yh, A=xh/xl) and hl (B=yl, A=xh). ll dropped (~1e-7).
#pragma unroll
    for (int s = 0; s < 4; ++s) {
        const uint32_t kb = (uint32_t)s * 32u;
        uint32_t A[2][2][4];   // [split][mt][frag]
#pragma unroll
        for (int t2 = 0; t2 < 2; ++t2) {
            const uint32_t xb = sbase + (uint32_t)t2 * 16384u;
#pragma unroll
            for (int mt = 0; mt < 2; ++mt) {
                uint32_t o = a_pre[mt] + kb; o ^= (o >> 3) & 0x70u;
                ldsm4(A[t2][mt][0], A[t2][mt][1], A[t2][mt][2], A[t2][mt][3], xb + o);
            }
        }
        uint32_t B[8][2];
        // B = yh: terms hh (A[0]) and lh (A[1])
#pragma unroll
        for (int p4 = 0; p4 < 4; ++p4) {
            uint32_t o = b_pre[p4] + kb; o ^= (o >> 3) & 0x70u;
            ldsm4(B[2 * p4][0], B[2 * p4][1], B[2 * p4 + 1][0], B[2 * p4 + 1][1],
                  sbase + 32768u + o);
        }
#pragma unroll
        for (int nt = 0; nt < 8; ++nt)
#pragma unroll
            for (int mt = 0; mt < 2; ++mt) {
                mma_f16(acc[mt][nt][0], acc[mt][nt][1], acc[mt][nt][2], acc[mt][nt][3],
                        A[0][mt][0], A[0][mt][1], A[0][mt][2], A[0][mt][3],
                        B[nt][0], B[nt][1]);
                mma_f16(acc[mt][nt][0], acc[mt][nt][1], acc[mt][nt][2], acc[mt][nt][3],
                        A[1][mt][0], A[1][mt][1], A[1][mt][2], A[1][mt][3],
                        B[nt][0], B[nt][1]);
            }
        // B = yl: term hl (A[0] only)
#pragma unroll
        for (int p4 = 0; p4 < 4; ++p4) {
            uint32_t o = b_pre[p4] + kb; o ^= (o >> 3) & 0x70u;
            ldsm4(B[2 * p4][0], B[2 * p4][1], B[2 * p4 + 1][0], B[2 * p4 + 1][1],
                  sbase + 49152u + o);
        }
#pragma unroll
        for (int nt = 0; nt < 8; ++nt)
#pragma unroll
            for (int mt = 0; mt < 2; ++mt) {
                mma_f16(acc[mt][nt][0], acc[mt][nt][1], acc[mt][nt][2], acc[mt][nt][3],
                        A[0][mt][0], A[0][mt][1], A[0][mt][2], A[0][mt][3],
                        B[nt][0], B[nt][1]);
            }
    }

    // ---------------- fused epilogue ----------------
    // C frag: lane: rows (l>>2), (l>>2)+8 per m-tile; cols 2*(l&3), +1 per n-tile
    const int q = lane & 3;
    const int lr = lane >> 2;
    float rsum[4] = {0.f, 0.f, 0.f, 0.f};
    unsigned rkey[4] = {0u, 0u, 0u, 0u};
    unsigned rcol[4] = {0u, 0u, 0u, 0u};
    float xqv[4];
#pragma unroll
    for (int ridx = 0; ridx < 4; ++ridx)
        xqv[ridx] = s_sxq[mblk + (ridx >> 1) * 16 + (ridx & 1) * 8 + lr];

#pragma unroll
    for (int nt = 0; nt < 8; ++nt) {
        float csum0 = 0.f, csum1 = 0.f;
        unsigned long long cmax0 = 0ull, cmax1 = 0ull;
        const int cbase = nblk + nt * 8 + 2 * q;
        const float yq0 = s_syq[cbase];
        const float yq1 = s_syq[cbase + 1];
#pragma unroll
        for (int mt = 0; mt < 2; ++mt) {
#pragma unroll
            for (int h = 0; h < 2; ++h) {
                const int ridx = mt * 2 + h;
                const unsigned grow = (unsigned)(ibase + mblk + mt * 16 + h * 8 + lr);
                const float xs = xqv[ridx];
#pragma unroll
                for (int u = 0; u < 2; ++u) {
                    float a = acc[mt][nt][h * 2 + u];
                    float yq = u ? yq1 : yq0;
                    float sq = fmaxf(fmaf(-2.f, a, xs + yq), 0.f);
                    float dist = sqrtf(sq);
                    unsigned key = fkey(2.f - dist);
                    float p = __expf(-dist);
                    rsum[ridx] += p;
                    if (key > rkey[ridx]) { rkey[ridx] = key; rcol[ridx] = (unsigned)(jbase + cbase + u); }
                    unsigned long long pc = (((unsigned long long)key) << 32) |
                                            (unsigned long long)(~grow);
                    if (u) { csum1 += p; if (pc > cmax1) cmax1 = pc; }
                    else   { csum0 += p; if (pc > cmax0) cmax0 = pc; }
                }
            }
        }
        // butterfly over the 8 lanes sharing q (offsets 4, 8, 16)
#pragma unroll
        for (int off = 4; off < 32; off <<= 1) {
            csum0 += __shfl_xor_sync(0xFFFFFFFFu, csum0, off);
            csum1 += __shfl_xor_sync(0xFFFFFFFFu, csum1, off);
            unsigned long long o0 = __shfl_xor_sync(0xFFFFFFFFu, cmax0, off);
            unsigned long long o1 = __shfl_xor_sync(0xFFFFFFFFu, cmax1, off);
            if (o0 > cmax0) cmax0 = o0;
            if (o1 > cmax1) cmax1 = o1;
        }
        if (lane < 4) {
            atomicAdd(&s_csum[cbase], csum0);
            atomicAdd(&s_csum[cbase + 1], csum1);
            atomicMax(&s_cmax[cbase], cmax0);
            atomicMax(&s_cmax[cbase + 1], cmax1);
        }
    }
    // row reduction over the 4 lanes sharing lr (offsets 1, 2)
#pragma unroll
    for (int ridx = 0; ridx < 4; ++ridx) {
        unsigned long long rp = (((unsigned long long)rkey[ridx]) << 32) |
                                (unsigned long long)(~rcol[ridx]);
        float rs = rsum[ridx];
#pragma unroll
        for (int off = 1; off < 4; off <<= 1) {
            rs += __shfl_xor_sync(0xFFFFFFFFu, rs, off);
            unsigned long long o = __shfl_xor_sync(0xFFFFFFFFu, rp, off);
            if (o > rp) rp = o;
        }
        if (q == 0) {
            int r = mblk + (ridx >> 1) * 16 + (ridx & 1) * 8 + lr;
            atomicAdd(&s_rsum[r], rs);
            atomicMax(&s_rmax[r], rp);
        }
    }
    __syncthreads();
    if (tid < 128) {
        atomicAdd(&g_colsum[jbase + tid], s_csum[tid]);
        atomicMax(&g_colmaxp[jbase + tid], s_cmax[tid]);
        atomicAdd(&g_rowsum[ibase + tid], s_rsum[tid]);
        atomicMax(&g_rowmaxp[ibase + tid], s_rmax[tid]);
    }
}

// ---------------- finalize 1: per-row/col lse, choice, lp ----------------
__global__ void finalize1_kernel() {
    int t = blockIdx.x * blockDim.x + threadIdx.x;
    if (t >= NN) return;
    {
        unsigned long long p = g_rowmaxp[t];
        float Dmax = unfkey((unsigned)(p >> 32));
        g_choice_rows[t] = (int)(~(unsigned)(p & 0xFFFFFFFFull));
        g_lp_rows[t] = Dmax - (2.f + logf(g_rowsum[t]));
    }
    {
        unsigned long long p = g_colmaxp[t];
        float Dmax = unfkey((unsigned)(p >> 32));
        g_choice_cols[t] = (int)(~(unsigned)(p & 0xFFFFFFFFull));
        g_lp_cols[t] = Dmax - (2.f + logf(g_colsum[t]));
    }
}

// ---------------- finalize 2: mutual match + outputs ----------------
// out (float32): [0:M) log_probs, [M:3M) dmatches (cc, j), [3M:4M) mutual
__global__ void finalize2_kernel(float* __restrict__ out) {
    int j = blockIdx.x * blockDim.x + threadIdx.x;
    if (j >= MM) return;
    int cc = g_choice_cols[j];
    bool mut = (g_choice_rows[cc] == j);
    out[j] = mut ? (g_lp_rows[cc] + g_lp_cols[j]) : 0.f;
    out[MM + 2 * j]     = (float)cc;
    out[MM + 2 * j + 1] = (float)j;
    out[3 * MM + j] = mut ? 1.f : 0.f;
}

extern "C" void kernel_launch(void* const* d_in, const int* in_sizes, int n_in,
                              void* d_out, int out_size) {
    const float* x = (const float*)d_in[0];
    const float* y = (const float*)d_in[1];
    float* out = (float*)d_out;

    static int smem_set = 0;
    if (!smem_set) {
        cudaFuncSetAttribute(matcher_main_kernel,
                             cudaFuncAttributeMaxDynamicSharedMemorySize, SMEM_TOTAL);
        smem_set = 1;
    }

    prep_kernel<<<(2 * NN + 255) / 256, 256>>>(x, y);
    dim3 grid(NTILE, NTILE);
    matcher_main_kernel<<<grid, 256, SMEM_TOTAL>>>();
    finalize1_kernel<<<(NN + 255) / 256, 256>>>();
    finalize2_kernel<<<(MM + 255) / 256, 256>>>(out);
}

// round 15
// speedup vs baseline: 1.1343x; 1.1343x over previous
#include <cuda_runtime.h>
#include <cuda_fp16.h>
#include <stdint.h>

// Problem constants
#define NN 8192
#define MM 8192
#define DD 64
#define TIM 256            // i-rows per CTA tile
#define TJN 128            // j-cols per CTA tile
#define NTI (NN / TIM)     // 32
#define NTJ (MM / TJN)     // 64

// ---------------- device scratch ----------------
__device__ uint4 g_xh[NN * 8];
__device__ uint4 g_xl[NN * 8];
__device__ uint4 g_yh[NN * 8];
__device__ uint4 g_yl[NN * 8];

__device__ float g_xsq[NN];
__device__ float g_ysq[MM];
__device__ float g_rowsum[NN];
__device__ float g_colsum[MM];
__device__ unsigned long long g_rowmaxp[NN];
__device__ unsigned long long g_colmaxp[MM];
__device__ float g_lp_rows[NN];
__device__ float g_lp_cols[MM];
__device__ int   g_choice_rows[NN];
__device__ int   g_choice_cols[MM];

// ---------------- helpers ----------------
__device__ __forceinline__ unsigned fkey(float f) {
    unsigned u = __float_as_uint(f);
    return u ^ ((unsigned)(((int)u) >> 31) | 0x80000000u);
}
__device__ __forceinline__ float unfkey(unsigned k) {
    unsigned u = (k & 0x80000000u) ? (k ^ 0x80000000u) : ~k;
    return __uint_as_float(u);
}
__device__ __forceinline__ void ffma2(unsigned long long& d,
                                      unsigned long long a,
                                      unsigned long long b) {
    asm("fma.rn.f32x2 %0, %1, %2, %0;" : "+l"(d) : "l"(a), "l"(b));
}
__device__ __forceinline__ unsigned long long bcast2(float a) {
    unsigned long long r;
    asm("mov.b64 %0, {%1, %1};" : "=l"(r) : "f"(a));
    return r;
}
__device__ __forceinline__ void unpack2(float& lo, float& hi, unsigned long long v) {
    asm("mov.b64 {%0, %1}, %2;" : "=f"(lo), "=f"(hi) : "l"(v));
}
__device__ __forceinline__ uint32_t smem_u32(const void* p) {
    uint32_t a;
    asm("{ .reg .u64 t; cvta.to.shared.u64 t, %1; cvt.u32.u64 %0, t; }"
        : "=r"(a) : "l"(p));
    return a;
}
__device__ __forceinline__ void ldsm4(uint32_t& r0, uint32_t& r1, uint32_t& r2,
                                      uint32_t& r3, uint32_t addr) {
    asm volatile("ldmatrix.sync.aligned.m8n8.x4.shared.b16 {%0,%1,%2,%3}, [%4];"
                 : "=r"(r0), "=r"(r1), "=r"(r2), "=r"(r3) : "r"(addr));
}
__device__ __forceinline__ void mma_f16(float& d0, float& d1, float& d2, float& d3,
                                        uint32_t a0, uint32_t a1, uint32_t a2, uint32_t a3,
                                        uint32_t b0, uint32_t b1) {
    asm("mma.sync.aligned.m16n8k16.row.col.f32.f16.f16.f32 "
        "{%0,%1,%2,%3}, {%4,%5,%6,%7}, {%8,%9}, {%0,%1,%2,%3};"
        : "+f"(d0), "+f"(d1), "+f"(d2), "+f"(d3)
        : "r"(a0), "r"(a1), "r"(a2), "r"(a3), "r"(b0), "r"(b1));
}

// ---------------- prep: zero accums, sqnorms, fp16 2-way split ----------------
__global__ void prep_kernel(const float* __restrict__ x, const float* __restrict__ y) {
    int t = blockIdx.x * blockDim.x + threadIdx.x;
    if (t < NN) {
        g_rowsum[t] = 0.f; g_colsum[t] = 0.f;
        g_rowmaxp[t] = 0ull; g_colmaxp[t] = 0ull;
    }
    if (t >= 2 * NN) return;
    int r = (t < NN) ? t : (t - NN);
    const float* src = (t < NN) ? (x + (size_t)r * DD) : (y + (size_t)r * DD);
    __half2* ph = ((t < NN) ? (__half2*)g_xh : (__half2*)g_yh) + (size_t)r * 32;
    __half2* pl = ((t < NN) ? (__half2*)g_xl : (__half2*)g_yl) + (size_t)r * 32;

    float s = 0.f;
#pragma unroll
    for (int k = 0; k < 32; ++k) {
        float2 v = ((const float2*)src)[k];
        s += v.x * v.x + v.y * v.y;
        __half ha = __float2half(v.x);
        __half la = __float2half(v.x - __half2float(ha));
        __half hb = __float2half(v.y);
        __half lb = __float2half(v.y - __half2float(hb));
        __half2 vh; vh.x = ha; vh.y = hb;
        __half2 vl; vl.x = la; vl.y = lb;
        ph[k] = vh; pl[k] = vl;
    }
    if (t < NN) g_xsq[r] = s; else g_ysq[r] = s;
}

// ---------------- smem layout ----------------
// H fp16 tiles (SW128, 128B rows): xh/xl rows 64..255 (192 rows), yh/yl 128 rows
#define S_XH   0                     // 24576
#define S_XL   24576                 // 24576
#define S_YH   49152                 // 16384
#define S_YL   65536                 // 16384
#define S_XT   81920                 // fp32 x transposed [64 d][72] = 18432
#define S_YT   100352                // fp32 y transposed [64 d][132] = 33792
#define S_SXQ  134144                // 256 floats
#define S_SYQ  135168                // 128 floats
#define S_CSUM 135680                // 128 floats
#define S_CMAX 136192                // 128 u64
#define SMEM_TOTAL 137216

#define XTS 72
#define YTS 132

// ---------------- main: warp-specialized F(FFMA2 fp32) + H(3-term fp16 mma) ----------------
__global__ void __launch_bounds__(512, 1)
matcher_main_kernel(const float* __restrict__ x, const float* __restrict__ y) {
    extern __shared__ char smem[];
    uint32_t sbase = smem_u32(smem);
    const int tid = threadIdx.x;
    const int w = tid >> 5;
    const int lane = tid & 31;
    const int ibase = blockIdx.y * TIM;
    const int jbase = blockIdx.x * TJN;

    float* xT = (float*)(smem + S_XT);
    float* yT = (float*)(smem + S_YT);
    float* s_sxq = (float*)(smem + S_SXQ);
    float* s_syq = (float*)(smem + S_SYQ);
    float* s_csum = (float*)(smem + S_CSUM);
    unsigned long long* s_cmax = (unsigned long long*)(smem + S_CMAX);

    // ---------- cooperative load phase (all 512 threads) ----------
    // fp16 x tiles: rows ibase+64 .. ibase+255 (192 rows)
    for (int idx = tid; idx < 192 * 8; idx += 512) {
        int row = idx >> 3, c = idx & 7;
        uint32_t bo = (uint32_t)(row * 128 + c * 16);
        uint32_t so = bo ^ ((bo >> 3) & 0x70u);
        *(uint4*)(smem + S_XH + so) = g_xh[(size_t)(ibase + 64 + row) * 8 + c];
        *(uint4*)(smem + S_XL + so) = g_xl[(size_t)(ibase + 64 + row) * 8 + c];
    }
    // fp16 y tiles: 128 rows
    for (int idx = tid; idx < 128 * 8; idx += 512) {
        int row = idx >> 3, c = idx & 7;
        uint32_t bo = (uint32_t)(row * 128 + c * 16);
        uint32_t so = bo ^ ((bo >> 3) & 0x70u);
        *(uint4*)(smem + S_YH + so) = g_yh[(size_t)(jbase + row) * 8 + c];
        *(uint4*)(smem + S_YL + so) = g_yl[(size_t)(jbase + row) * 8 + c];
    }
    // fp32 xT transposed: rows ibase..ibase+63
    for (int k = tid; k < 64 * 16; k += 512) {
        int r = k >> 4, c4 = k & 15;
        float4 v = *(const float4*)(x + (size_t)(ibase + r) * DD + c4 * 4);
        int d = c4 * 4;
        xT[(d + 0) * XTS + r] = v.x;
        xT[(d + 1) * XTS + r] = v.y;
        xT[(d + 2) * XTS + r] = v.z;
        xT[(d + 3) * XTS + r] = v.w;
    }
    // fp32 yT transposed: 128 rows
    for (int k = tid; k < 128 * 16; k += 512) {
        int r = k >> 4, c4 = k & 15;
        float4 v = *(const float4*)(y + (size_t)(jbase + r) * DD + c4 * 4);
        int d = c4 * 4;
        yT[(d + 0) * YTS + r] = v.x;
        yT[(d + 1) * YTS + r] = v.y;
        yT[(d + 2) * YTS + r] = v.z;
        yT[(d + 3) * YTS + r] = v.w;
    }
    if (tid < 256) s_sxq[tid] = g_xsq[ibase + tid];
    else if (tid < 384) s_syq[tid - 256] = g_ysq[jbase + tid - 256];
    else if (tid < 512) { s_csum[tid - 384] = 0.f; s_cmax[tid - 384] = 0ull; }
    __syncthreads();

    if (w < 4) {
        // ================= F: rows 0..63, FFMA2 fp32 (R12-verified) =================
        const int tx = tid & 15;
        const int ty = tid >> 4;          // 0..7
        const int i0 = ty * 8;
        const int j0 = tx * 8;

        unsigned long long acc2[8][4];
#pragma unroll
        for (int r = 0; r < 8; ++r)
#pragma unroll
            for (int c2 = 0; c2 < 4; ++c2) acc2[r][c2] = 0ull;

#pragma unroll 4
        for (int d = 0; d < DD; ++d) {
            ulonglong2 p0 = *(const ulonglong2*)&yT[d * YTS + j0];
            ulonglong2 p1 = *(const ulonglong2*)&yT[d * YTS + j0 + 4];
            unsigned long long bp[4] = { p0.x, p0.y, p1.x, p1.y };
            float4 t0 = *(const float4*)&xT[d * XTS + i0];
            float4 t1 = *(const float4*)&xT[d * XTS + i0 + 4];
            unsigned long long av[8];
            av[0] = bcast2(t0.x); av[1] = bcast2(t0.y);
            av[2] = bcast2(t0.z); av[3] = bcast2(t0.w);
            av[4] = bcast2(t1.x); av[5] = bcast2(t1.y);
            av[6] = bcast2(t1.z); av[7] = bcast2(t1.w);
#pragma unroll
            for (int r = 0; r < 8; ++r)
#pragma unroll
                for (int c2 = 0; c2 < 4; ++c2)
                    ffma2(acc2[r][c2], av[r], bp[c2]);
        }

        float rsum[8];
        unsigned long long rpack[8];
        float csum[8];
        unsigned long long cpack[8];
#pragma unroll
        for (int r = 0; r < 8; ++r) { rsum[r] = 0.f; rpack[r] = 0ull; }
#pragma unroll
        for (int c = 0; c < 8; ++c) { csum[c] = 0.f; cpack[c] = 0ull; }

#pragma unroll
        for (int r = 0; r < 8; ++r) {
            float xq = s_sxq[i0 + r];
            unsigned inv_i = ~(unsigned)(ibase + i0 + r);
#pragma unroll
            for (int c2 = 0; c2 < 4; ++c2) {
                float a0, a1;
                unpack2(a0, a1, acc2[r][c2]);
#pragma unroll
                for (int u = 0; u < 2; ++u) {
                    const int c = 2 * c2 + u;
                    float acc = u ? a1 : a0;
                    float sq = s_syq[j0 + c] + xq - 2.f * acc;
                    float dist = sqrtf(fmaxf(sq, 0.f));
                    float Dm = 2.f - dist;
                    float p = __expf(-dist);
                    rsum[r] += p;
                    csum[c] += p;
                    unsigned long long key = ((unsigned long long)fkey(Dm)) << 32;
                    unsigned long long pr = key | (unsigned)~(unsigned)(jbase + j0 + c);
                    unsigned long long pc = key | inv_i;
                    if (pr > rpack[r]) rpack[r] = pr;
                    if (pc > cpack[c]) cpack[c] = pc;
                }
            }
        }
        // row reduce across tx (16-lane half-warp groups)
#pragma unroll
        for (int r = 0; r < 8; ++r) {
#pragma unroll
            for (int off = 8; off >= 1; off >>= 1) {
                rsum[r] += __shfl_xor_sync(0xFFFFFFFFu, rsum[r], off);
                unsigned long long o = __shfl_xor_sync(0xFFFFFFFFu, rpack[r], off);
                if (o > rpack[r]) rpack[r] = o;
            }
        }
        if (tx == 0) {
#pragma unroll
            for (int r = 0; r < 8; ++r) {
                atomicAdd(&g_rowsum[ibase + i0 + r], rsum[r]);
                atomicMax(&g_rowmaxp[ibase + i0 + r], rpack[r]);
            }
        }
        // col partials -> shared smem accumulators
#pragma unroll
        for (int c = 0; c < 8; ++c) {
            atomicAdd(&s_csum[j0 + c], csum[c]);
            atomicMax(&s_cmax[j0 + c], cpack[c]);
        }
    } else {
        // ================= H: rows 64..255, 3-term fp16 mma (R14-verified) =================
        const int sr = (w - 4) * 16;          // strip base within 192-row x tile
        const int mi = lane >> 3;
        const int l7 = lane & 7;

        const uint32_t a_pre = (uint32_t)((sr + (mi & 1) * 8 + l7) * 128 + (mi >> 1) * 16);
        uint32_t b_pre[8];
#pragma unroll
        for (int p = 0; p < 8; ++p)
            b_pre[p] = (uint32_t)((p * 16 + (mi >> 1) * 8 + l7) * 128 + (mi & 1) * 16);

        float acc[16][4];
#pragma unroll
        for (int nt = 0; nt < 16; ++nt)
#pragma unroll
            for (int k = 0; k < 4; ++k) acc[nt][k] = 0.f;

#pragma unroll
        for (int s = 0; s < 4; ++s) {
            const uint32_t kb = (uint32_t)s * 32u;
            uint32_t A0[4], A1[4];
            {
                uint32_t o = a_pre + kb; o ^= (o >> 3) & 0x70u;
                ldsm4(A0[0], A0[1], A0[2], A0[3], sbase + S_XH + o);
                ldsm4(A1[0], A1[1], A1[2], A1[3], sbase + S_XL + o);
            }
#pragma unroll
            for (int ng = 0; ng < 4; ++ng) {
                uint32_t B[4][2];
#pragma unroll
                for (int v = 0; v < 2; ++v) {
                    uint32_t o = b_pre[ng * 2 + v] + kb; o ^= (o >> 3) & 0x70u;
                    ldsm4(B[2 * v][0], B[2 * v][1], B[2 * v + 1][0], B[2 * v + 1][1],
                          sbase + S_YH + o);
                }
#pragma unroll
                for (int t = 0; t < 4; ++t) {
                    float* a = acc[ng * 4 + t];
                    mma_f16(a[0], a[1], a[2], a[3],
                            A0[0], A0[1], A0[2], A0[3], B[t][0], B[t][1]);
                    mma_f16(a[0], a[1], a[2], a[3],
                            A1[0], A1[1], A1[2], A1[3], B[t][0], B[t][1]);
                }
#pragma unroll
                for (int v = 0; v < 2; ++v) {
                    uint32_t o = b_pre[ng * 2 + v] + kb; o ^= (o >> 3) & 0x70u;
                    ldsm4(B[2 * v][0], B[2 * v][1], B[2 * v + 1][0], B[2 * v + 1][1],
                          sbase + S_YL + o);
                }
#pragma unroll
                for (int t = 0; t < 4; ++t) {
                    float* a = acc[ng * 4 + t];
                    mma_f16(a[0], a[1], a[2], a[3],
                            A0[0], A0[1], A0[2], A0[3], B[t][0], B[t][1]);
                }
            }
        }

        // fused epilogue for the 16-row strip
        const int q = lane & 3;
        const int lr = lane >> 2;
        float rsum[2] = {0.f, 0.f};
        unsigned rkey[2] = {0u, 0u};
        unsigned rcol[2] = {0u, 0u};
        const float xq0 = s_sxq[64 + sr + lr];
        const float xq1 = s_sxq[64 + sr + 8 + lr];

#pragma unroll
        for (int nt = 0; nt < 16; ++nt) {
            float csum0 = 0.f, csum1 = 0.f;
            unsigned long long cmax0 = 0ull, cmax1 = 0ull;
            const int cbase = nt * 8 + 2 * q;
            const float yq0 = s_syq[cbase];
            const float yq1 = s_syq[cbase + 1];
#pragma unroll
            for (int h = 0; h < 2; ++h) {
                const unsigned grow = (unsigned)(ibase + 64 + sr + h * 8 + lr);
                const float xs = h ? xq1 : xq0;
#pragma unroll
                for (int u = 0; u < 2; ++u) {
                    float a = acc[nt][h * 2 + u];
                    float yq = u ? yq1 : yq0;
                    float sq = fmaxf(fmaf(-2.f, a, xs + yq), 0.f);
                    float dist = sqrtf(sq);
                    unsigned key = fkey(2.f - dist);
                    float p = __expf(-dist);
                    rsum[h] += p;
                    if (key > rkey[h]) { rkey[h] = key; rcol[h] = (unsigned)(jbase + cbase + u); }
                    unsigned long long pc = (((unsigned long long)key) << 32) |
                                            (unsigned long long)(~grow);
                    if (u) { csum1 += p; if (pc > cmax1) cmax1 = pc; }
                    else   { csum0 += p; if (pc > cmax0) cmax0 = pc; }
                }
            }
            // butterfly over the 8 lanes sharing q (offsets 4, 8, 16)
#pragma unroll
            for (int off = 4; off < 32; off <<= 1) {
                csum0 += __shfl_xor_sync(0xFFFFFFFFu, csum0, off);
                csum1 += __shfl_xor_sync(0xFFFFFFFFu, csum1, off);
                unsigned long long o0 = __shfl_xor_sync(0xFFFFFFFFu, cmax0, off);
                unsigned long long o1 = __shfl_xor_sync(0xFFFFFFFFu, cmax1, off);
                if (o0 > cmax0) cmax0 = o0;
                if (o1 > cmax1) cmax1 = o1;
            }
            if (lane < 4) {
                atomicAdd(&s_csum[cbase], csum0);
                atomicAdd(&s_csum[cbase + 1], csum1);
                atomicMax(&s_cmax[cbase], cmax0);
                atomicMax(&s_cmax[cbase + 1], cmax1);
            }
        }
        // row reduction over the 4 lanes sharing lr (offsets 1, 2)
#pragma unroll
        for (int h = 0; h < 2; ++h) {
            unsigned long long rp = (((unsigned long long)rkey[h]) << 32) |
                                    (unsigned long long)(~rcol[h]);
            float rs = rsum[h];
#pragma unroll
            for (int off = 1; off < 4; off <<= 1) {
                rs += __shfl_xor_sync(0xFFFFFFFFu, rs, off);
                unsigned long long o = __shfl_xor_sync(0xFFFFFFFFu, rp, off);
                if (o > rp) rp = o;
            }
            if (q == 0) {
                int r = ibase + 64 + sr + h * 8 + lr;
                atomicAdd(&g_rowsum[r], rs);
                atomicMax(&g_rowmaxp[r], rp);
            }
        }
    }

    __syncthreads();
    if (tid < 128) {
        atomicAdd(&g_colsum[jbase + tid], s_csum[tid]);
        atomicMax(&g_colmaxp[jbase + tid], s_cmax[tid]);
    }
}

// ---------------- finalize 1: per-row/col lse, choice, lp ----------------
__global__ void finalize1_kernel() {
    int t = blockIdx.x * blockDim.x + threadIdx.x;
    if (t >= NN) return;
    {
        unsigned long long p = g_rowmaxp[t];
        float Dmax = unfkey((unsigned)(p >> 32));
        g_choice_rows[t] = (int)(~(unsigned)(p & 0xFFFFFFFFull));
        g_lp_rows[t] = Dmax - (2.f + logf(g_rowsum[t]));
    }
    {
        unsigned long long p = g_colmaxp[t];
        float Dmax = unfkey((unsigned)(p >> 32));
        g_choice_cols[t] = (int)(~(unsigned)(p & 0xFFFFFFFFull));
        g_lp_cols[t] = Dmax - (2.f + logf(g_colsum[t]));
    }
}

// ---------------- finalize 2: mutual match + outputs ----------------
// out (float32): [0:M) log_probs, [M:3M) dmatches (cc, j), [3M:4M) mutual
__global__ void finalize2_kernel(float* __restrict__ out) {
    int j = blockIdx.x * blockDim.x + threadIdx.x;
    if (j >= MM) return;
    int cc = g_choice_cols[j];
    bool mut = (g_choice_rows[cc] == j);
    out[j] = mut ? (g_lp_rows[cc] + g_lp_cols[j]) : 0.f;
    out[MM + 2 * j]     = (float)cc;
    out[MM + 2 * j + 1] = (float)j;
    out[3 * MM + j] = mut ? 1.f : 0.f;
}

extern "C" void kernel_launch(void* const* d_in, const int* in_sizes, int n_in,
                              void* d_out, int out_size) {
    const float* x = (const float*)d_in[0];
    const float* y = (const float*)d_in[1];
    float* out = (float*)d_out;

    static int smem_set = 0;
    if (!smem_set) {
        cudaFuncSetAttribute(matcher_main_kernel,
                             cudaFuncAttributeMaxDynamicSharedMemorySize, SMEM_TOTAL);
        smem_set = 1;
    }

    prep_kernel<<<(2 * NN + 255) / 256, 256>>>(x, y);
    dim3 grid(NTJ, NTI);
    matcher_main_kernel<<<grid, 512, SMEM_TOTAL>>>(x, y);
    finalize1_kernel<<<(NN + 255) / 256, 256>>>();
    finalize2_kernel<<<(MM + 255) / 256, 256>>>(out);
}

// round 16
// speedup vs baseline: 1.3381x; 1.1797x over previous
#include <cuda_runtime.h>
#include <cuda_fp16.h>
#include <stdint.h>

// Problem constants
#define NN 8192
#define MM 8192
#define DD 64
#define TILE 128
#define NTILE (NN / TILE)   // 64

// ---------------- device scratch ----------------
__device__ uint4 g_xh[NN * 8];
__device__ uint4 g_xl[NN * 8];
__device__ uint4 g_yh[NN * 8];
__device__ uint4 g_yl[NN * 8];

__device__ float g_xsq[NN];
__device__ float g_ysq[MM];
__device__ float g_rowsum[NN];
__device__ float g_colsum[MM];
__device__ unsigned long long g_rowmaxp[NN];
__device__ unsigned long long g_colmaxp[MM];
__device__ float g_lp_rows[NN];
__device__ float g_lp_cols[MM];
__device__ int   g_choice_rows[NN];
__device__ int   g_choice_cols[MM];

// ---------------- helpers ----------------
// key convention: dist >= 0, so bits(dist) are unsigned-ordered ascending in dist.
// key = ~bits(dist): larger key == smaller dist. dist = uint_as_float(~key).
__device__ __forceinline__ float ex2a(float x) {
    float y; asm("ex2.approx.ftz.f32 %0, %1;" : "=f"(y) : "f"(x)); return y;
}
__device__ __forceinline__ float sqrta(float x) {
    float y; asm("sqrt.approx.ftz.f32 %0, %1;" : "=f"(y) : "f"(x)); return y;
}
__device__ __forceinline__ void ffma2(unsigned long long& d,
                                      unsigned long long a,
                                      unsigned long long b) {
    asm("fma.rn.f32x2 %0, %1, %2, %0;" : "+l"(d) : "l"(a), "l"(b));
}
__device__ __forceinline__ unsigned long long bcast2(float a) {
    unsigned long long r;
    asm("mov.b64 %0, {%1, %1};" : "=l"(r) : "f"(a));
    return r;
}
__device__ __forceinline__ void unpack2(float& lo, float& hi, unsigned long long v) {
    asm("mov.b64 {%0, %1}, %2;" : "=f"(lo), "=f"(hi) : "l"(v));
}
__device__ __forceinline__ uint32_t smem_u32(const void* p) {
    uint32_t a;
    asm("{ .reg .u64 t; cvta.to.shared.u64 t, %1; cvt.u32.u64 %0, t; }"
        : "=r"(a) : "l"(p));
    return a;
}
__device__ __forceinline__ void ldsm4(uint32_t& r0, uint32_t& r1, uint32_t& r2,
                                      uint32_t& r3, uint32_t addr) {
    asm volatile("ldmatrix.sync.aligned.m8n8.x4.shared.b16 {%0,%1,%2,%3}, [%4];"
                 : "=r"(r0), "=r"(r1), "=r"(r2), "=r"(r3) : "r"(addr));
}
__device__ __forceinline__ void mma_f16(float& d0, float& d1, float& d2, float& d3,
                                        uint32_t a0, uint32_t a1, uint32_t a2, uint32_t a3,
                                        uint32_t b0, uint32_t b1) {
    asm("mma.sync.aligned.m16n8k16.row.col.f32.f16.f16.f32 "
        "{%0,%1,%2,%3}, {%4,%5,%6,%7}, {%8,%9}, {%0,%1,%2,%3};"
        : "+f"(d0), "+f"(d1), "+f"(d2), "+f"(d3)
        : "r"(a0), "r"(a1), "r"(a2), "r"(a3), "r"(b0), "r"(b1));
}

// ---------------- prep: zero accums, sqnorms, fp16 2-way split ----------------
__global__ void prep_kernel(const float* __restrict__ x, const float* __restrict__ y) {
    int t = blockIdx.x * blockDim.x + threadIdx.x;
    if (t < NN) {
        g_rowsum[t] = 0.f; g_colsum[t] = 0.f;
        g_rowmaxp[t] = 0ull; g_colmaxp[t] = 0ull;
    }
    if (t >= 2 * NN) return;
    int r = (t < NN) ? t : (t - NN);
    const float* src = (t < NN) ? (x + (size_t)r * DD) : (y + (size_t)r * DD);
    __half2* ph = ((t < NN) ? (__half2*)g_xh : (__half2*)g_yh) + (size_t)r * 32;
    __half2* pl = ((t < NN) ? (__half2*)g_xl : (__half2*)g_yl) + (size_t)r * 32;

    float s = 0.f;
#pragma unroll
    for (int k = 0; k < 32; ++k) {
        float2 v = ((const float2*)src)[k];
        s += v.x * v.x + v.y * v.y;
        __half ha = __float2half(v.x);
        __half la = __float2half(v.x - __half2float(ha));
        __half hb = __float2half(v.y);
        __half lb = __float2half(v.y - __half2float(hb));
        __half2 vh; vh.x = ha; vh.y = hb;
        __half2 vl; vl.x = la; vl.y = lb;
        ph[k] = vh; pl[k] = vl;
    }
    if (t < NN) g_xsq[r] = s; else g_ysq[r] = s;
}

// ---------------- smem layouts (union of the two methods) ----------------
// F (FFMA2) branch:
#define XT_STRIDE 132
#define F_XT 0
#define F_YT (F_XT + 64 * XT_STRIDE * 4)          // 33792
#define F_SXQ (F_YT + 64 * XT_STRIDE * 4)         // 67584
#define F_SYQ (F_SXQ + 512)
#define F_CSUM (F_SYQ + 512)
#define F_CMAX ((F_CSUM + 512 + 15) & ~15)
#define F_END (F_CMAX + 1024)                     // 70144
// H (mma.sync fp16) branch: 4 tiles (xh xl yh yl), 128 rows x 128B, SW128
#define H_SXQ  (4 * 16384)                        // 65536
#define H_SYQ  (H_SXQ + 512)
#define H_CSUM (H_SYQ + 512)
#define H_RSUM (H_CSUM + 512)
#define H_CMAX (H_RSUM + 512)
#define H_RMAX (H_CMAX + 1024)
#define H_END  (H_RMAX + 1024)                    // 69632
#define SMEM_TOTAL (F_END > H_END ? F_END : H_END)

// ---------------- main hybrid kernel ----------------
__global__ void __launch_bounds__(256, 2)
matcher_main_kernel(const float* __restrict__ x, const float* __restrict__ y) {
    extern __shared__ char smem[];
    const int tid = threadIdx.x;
    const int ibase = blockIdx.y * TILE;
    const int jbase = blockIdx.x * TILE;
    const int bid = blockIdx.y * gridDim.x + blockIdx.x;
    const int method = (bid / 148) & 1;

    if (method == 0) {
        // ================= F branch: FFMA2 fp32 =================
        float* xT = (float*)(smem + F_XT);
        float* yT = (float*)(smem + F_YT);
        float* sxq = (float*)(smem + F_SXQ);
        float* syq = (float*)(smem + F_SYQ);
        float* scsum = (float*)(smem + F_CSUM);
        unsigned long long* scmax = (unsigned long long*)(smem + F_CMAX);

        const int tx = tid & 15;
        const int ty = tid >> 4;
        const int i0 = ty * 8;
        const int j0 = tx * 8;

#pragma unroll
        for (int k = tid; k < TILE * (DD / 4); k += 256) {
            int r = k >> 4;
            int c4 = k & 15;
            float4 vx = *(const float4*)(x + (size_t)(ibase + r) * DD + c4 * 4);
            float4 vy = *(const float4*)(y + (size_t)(jbase + r) * DD + c4 * 4);
            int d = c4 * 4;
            xT[(d + 0) * XT_STRIDE + r] = vx.x;
            xT[(d + 1) * XT_STRIDE + r] = vx.y;
            xT[(d + 2) * XT_STRIDE + r] = vx.z;
            xT[(d + 3) * XT_STRIDE + r] = vx.w;
            yT[(d + 0) * XT_STRIDE + r] = vy.x;
            yT[(d + 1) * XT_STRIDE + r] = vy.y;
            yT[(d + 2) * XT_STRIDE + r] = vy.z;
            yT[(d + 3) * XT_STRIDE + r] = vy.w;
        }
        if (tid < 128) sxq[tid] = g_xsq[ibase + tid];
        else           syq[tid - 128] = g_ysq[jbase + tid - 128];
        __syncthreads();

        unsigned long long acc2[8][4];
#pragma unroll
        for (int r = 0; r < 8; ++r)
#pragma unroll
            for (int c2 = 0; c2 < 4; ++c2) acc2[r][c2] = 0ull;

#pragma unroll 4
        for (int d = 0; d < DD; ++d) {
            ulonglong2 p0 = *(const ulonglong2*)&yT[d * XT_STRIDE + j0];
            ulonglong2 p1 = *(const ulonglong2*)&yT[d * XT_STRIDE + j0 + 4];
            unsigned long long bp[4] = { p0.x, p0.y, p1.x, p1.y };
            float4 t0 = *(const float4*)&xT[d * XT_STRIDE + i0];
            float4 t1 = *(const float4*)&xT[d * XT_STRIDE + i0 + 4];
            unsigned long long av[8];
            av[0] = bcast2(t0.x); av[1] = bcast2(t0.y);
            av[2] = bcast2(t0.z); av[3] = bcast2(t0.w);
            av[4] = bcast2(t1.x); av[5] = bcast2(t1.y);
            av[6] = bcast2(t1.z); av[7] = bcast2(t1.w);
#pragma unroll
            for (int r = 0; r < 8; ++r)
#pragma unroll
                for (int c2 = 0; c2 < 4; ++c2)
                    ffma2(acc2[r][c2], av[r], bp[c2]);
        }

        // -------- slim epilogue: scalar (key32,idx) tracking --------
        float yqv[8];
#pragma unroll
        for (int c = 0; c < 8; ++c) yqv[c] = syq[j0 + c];

        float rsum[8], csum[8];
        unsigned rkey[8], rjc[8], ckey[8], cri[8];
#pragma unroll
        for (int r = 0; r < 8; ++r) { rsum[r] = 0.f; rkey[r] = 0u; rjc[r] = 0u; }
#pragma unroll
        for (int c = 0; c < 8; ++c) { csum[c] = 0.f; ckey[c] = 0u; cri[c] = 0u; }

#pragma unroll
        for (int r = 0; r < 8; ++r) {
            float xq = sxq[i0 + r];
#pragma unroll
            for (int c2 = 0; c2 < 4; ++c2) {
                float a0, a1;
                unpack2(a0, a1, acc2[r][c2]);
#pragma unroll
                for (int u = 0; u < 2; ++u) {
                    const int c = 2 * c2 + u;
                    float acc = u ? a1 : a0;
                    float sq = fmaxf(fmaf(-2.f, acc, xq + yqv[c]), 0.f);
                    float dist = sqrta(sq);
                    unsigned key = ~__float_as_uint(dist);
                    float pp = ex2a(-1.44269504f * dist);
                    rsum[r] += pp;
                    csum[c] += pp;
                    if (key > rkey[r]) { rkey[r] = key; rjc[r] = (unsigned)c; }
                    if (key > ckey[c]) { ckey[c] = key; cri[c] = (unsigned)r; }
                }
            }
        }

        // row reduce across tx (16-lane groups within warp)
#pragma unroll
        for (int r = 0; r < 8; ++r) {
            unsigned long long rp = (((unsigned long long)rkey[r]) << 32) |
                (unsigned long long)(unsigned)~(unsigned)(jbase + j0 + rjc[r]);
            float rs = rsum[r];
#pragma unroll
            for (int off = 8; off >= 1; off >>= 1) {
                rs += __shfl_xor_sync(0xFFFFFFFFu, rs, off);
                unsigned long long o = __shfl_xor_sync(0xFFFFFFFFu, rp, off);
                if (o > rp) rp = o;
            }
            if (tx == 0) {
                atomicAdd(&g_rowsum[ibase + i0 + r], rs);
                atomicMax(&g_rowmaxp[ibase + i0 + r], rp);
            }
        }
        // col reduce across ty via smem
        if (ty == 0) {
#pragma unroll
            for (int c = 0; c < 8; ++c) {
                scsum[j0 + c] = csum[c];
                scmax[j0 + c] = (((unsigned long long)ckey[c]) << 32) |
                    (unsigned long long)(unsigned)~(unsigned)(ibase + i0 + cri[c]);
            }
        }
        __syncthreads();
        if (ty != 0) {
#pragma unroll
            for (int c = 0; c < 8; ++c) {
                atomicAdd(&scsum[j0 + c], csum[c]);
                atomicMax(&scmax[j0 + c],
                          (((unsigned long long)ckey[c]) << 32) |
                          (unsigned long long)(unsigned)~(unsigned)(ibase + i0 + cri[c]));
            }
        }
        __syncthreads();
        if (ty == 0) {
#pragma unroll
            for (int c = 0; c < 8; ++c) {
                atomicAdd(&g_colsum[jbase + j0 + c], scsum[j0 + c]);
                atomicMax(&g_colmaxp[jbase + j0 + c], scmax[j0 + c]);
            }
        }
    } else {
        // ================= H branch: fp16 3-term mma.sync =================
        uint32_t sbase = smem_u32(smem);
        const int w = tid >> 5;
        const int lane = tid & 31;
        float* s_sxq = (float*)(smem + H_SXQ);
        float* s_syq = (float*)(smem + H_SYQ);
        float* s_csum = (float*)(smem + H_CSUM);
        float* s_rsum = (float*)(smem + H_RSUM);
        unsigned long long* s_cmax = (unsigned long long*)(smem + H_CMAX);
        unsigned long long* s_rmax = (unsigned long long*)(smem + H_RMAX);

#pragma unroll
        for (int t4 = 0; t4 < 4; ++t4) {
            const uint4* src = (t4 == 0) ? g_xh : (t4 == 1) ? g_xl
                             : (t4 == 2) ? g_yh : g_yl;
            int rbase = (t4 < 2) ? ibase : jbase;
            char* dst = smem + t4 * 16384;
            for (int k = tid; k < 1024; k += 256) {
                int row = k >> 3;
                int c = k & 7;
                uint4 v = src[(size_t)(rbase + row) * 8 + c];
                uint32_t bo = (uint32_t)(row * 128 + c * 16);
                *(uint4*)(dst + (bo ^ ((bo >> 3) & 0x70))) = v;
            }
        }
        if (tid < 128) {
            s_sxq[tid] = g_xsq[ibase + tid];
            s_syq[tid] = g_ysq[jbase + tid];
            s_csum[tid] = 0.f; s_rsum[tid] = 0.f;
            s_cmax[tid] = 0ull; s_rmax[tid] = 0ull;
        }
        __syncthreads();

        const int mblk = (w & 3) * 32;
        const int nblk = (w >> 2) * 64;
        const int mi = lane >> 3;
        const int l7 = lane & 7;

        uint32_t a_pre[2], b_pre[4];
#pragma unroll
        for (int mt = 0; mt < 2; ++mt)
            a_pre[mt] = (uint32_t)((mblk + mt * 16 + (mi & 1) * 8 + l7) * 128 + (mi >> 1) * 16);
#pragma unroll
        for (int p4 = 0; p4 < 4; ++p4)
            b_pre[p4] = (uint32_t)((nblk + p4 * 16 + (mi >> 1) * 8 + l7) * 128 + (mi & 1) * 16);

        float acc[2][8][4];
#pragma unroll
        for (int mt = 0; mt < 2; ++mt)
#pragma unroll
            for (int nt = 0; nt < 8; ++nt)
#pragma unroll
                for (int k = 0; k < 4; ++k) acc[mt][nt][k] = 0.f;

        // 3 terms: hh + lh (B=yh) and hl (B=yl); dependent same-acc MMAs split apart
#pragma unroll
        for (int s = 0; s < 4; ++s) {
            const uint32_t kb = (uint32_t)s * 32u;
            uint32_t A[2][2][4];
#pragma unroll
            for (int t2 = 0; t2 < 2; ++t2) {
                const uint32_t xb = sbase + (uint32_t)t2 * 16384u;
#pragma unroll
                for (int mt = 0; mt < 2; ++mt) {
                    uint32_t o = a_pre[mt] + kb; o ^= (o >> 3) & 0x70u;
                    ldsm4(A[t2][mt][0], A[t2][mt][1], A[t2][mt][2], A[t2][mt][3], xb + o);
                }
            }
            uint32_t B[8][2];
#pragma unroll
            for (int p4 = 0; p4 < 4; ++p4) {
                uint32_t o = b_pre[p4] + kb; o ^= (o >> 3) & 0x70u;
                ldsm4(B[2 * p4][0], B[2 * p4][1], B[2 * p4 + 1][0], B[2 * p4 + 1][1],
                      sbase + 32768u + o);
            }
            // hh sweep (all independent), then lh sweep (distance 16 from pair)
#pragma unroll
            for (int nt = 0; nt < 8; ++nt)
#pragma unroll
                for (int mt = 0; mt < 2; ++mt)
                    mma_f16(acc[mt][nt][0], acc[mt][nt][1], acc[mt][nt][2], acc[mt][nt][3],
                            A[0][mt][0], A[0][mt][1], A[0][mt][2], A[0][mt][3],
                            B[nt][0], B[nt][1]);
#pragma unroll
            for (int nt = 0; nt < 8; ++nt)
#pragma unroll
                for (int mt = 0; mt < 2; ++mt)
                    mma_f16(acc[mt][nt][0], acc[mt][nt][1], acc[mt][nt][2], acc[mt][nt][3],
                            A[1][mt][0], A[1][mt][1], A[1][mt][2], A[1][mt][3],
                            B[nt][0], B[nt][1]);
            // hl sweep
#pragma unroll
            for (int p4 = 0; p4 < 4; ++p4) {
                uint32_t o = b_pre[p4] + kb; o ^= (o >> 3) & 0x70u;
                ldsm4(B[2 * p4][0], B[2 * p4][1], B[2 * p4 + 1][0], B[2 * p4 + 1][1],
                      sbase + 49152u + o);
            }
#pragma unroll
            for (int nt = 0; nt < 8; ++nt)
#pragma unroll
                for (int mt = 0; mt < 2; ++mt)
                    mma_f16(acc[mt][nt][0], acc[mt][nt][1], acc[mt][nt][2], acc[mt][nt][3],
                            A[0][mt][0], A[0][mt][1], A[0][mt][2], A[0][mt][3],
                            B[nt][0], B[nt][1]);
        }

        // -------- slim fused epilogue --------
        const int q = lane & 3;
        const int lr = lane >> 2;
        float rsum[4] = {0.f, 0.f, 0.f, 0.f};
        unsigned rkey[4] = {0u, 0u, 0u, 0u};
        unsigned rjc[4] = {0u, 0u, 0u, 0u};
        float xqv[4];
#pragma unroll
        for (int ridx = 0; ridx < 4; ++ridx)
            xqv[ridx] = s_sxq[mblk + (ridx >> 1) * 16 + (ridx & 1) * 8 + lr];

#pragma unroll
        for (int nt = 0; nt < 8; ++nt) {
            float csum0 = 0.f, csum1 = 0.f;
            unsigned ck0 = 0u, ck1 = 0u, ci0 = 0u, ci1 = 0u;
            const int cbase = nblk + nt * 8 + 2 * q;
            const float yq0 = s_syq[cbase];
            const float yq1 = s_syq[cbase + 1];
#pragma unroll
            for (int mt = 0; mt < 2; ++mt) {
#pragma unroll
                for (int h = 0; h < 2; ++h) {
                    const int ridx = mt * 2 + h;
                    const unsigned rloc = (unsigned)(mblk + mt * 16 + h * 8 + lr);
                    const float xs = xqv[ridx];
#pragma unroll
                    for (int u = 0; u < 2; ++u) {
                        float a = acc[mt][nt][h * 2 + u];
                        float yq = u ? yq1 : yq0;
                        float sq = fmaxf(fmaf(-2.f, a, xs + yq), 0.f);
                        float dist = sqrta(sq);
                        unsigned key = ~__float_as_uint(dist);
                        float pp = ex2a(-1.44269504f * dist);
                        rsum[ridx] += pp;
                        if (key > rkey[ridx]) { rkey[ridx] = key; rjc[ridx] = (unsigned)(cbase + u); }
                        if (u) { csum1 += pp; if (key > ck1) { ck1 = key; ci1 = rloc; } }
                        else   { csum0 += pp; if (key > ck0) { ck0 = key; ci0 = rloc; } }
                    }
                }
            }
            unsigned long long cmax0 = (((unsigned long long)ck0) << 32) |
                (unsigned long long)(unsigned)~(unsigned)(ibase + ci0);
            unsigned long long cmax1 = (((unsigned long long)ck1) << 32) |
                (unsigned long long)(unsigned)~(unsigned)(ibase + ci1);
#pragma unroll
            for (int off = 4; off < 32; off <<= 1) {
                csum0 += __shfl_xor_sync(0xFFFFFFFFu, csum0, off);
                csum1 += __shfl_xor_sync(0xFFFFFFFFu, csum1, off);
                unsigned long long o0 = __shfl_xor_sync(0xFFFFFFFFu, cmax0, off);
                unsigned long long o1 = __shfl_xor_sync(0xFFFFFFFFu, cmax1, off);
                if (o0 > cmax0) cmax0 = o0;
                if (o1 > cmax1) cmax1 = o1;
            }
            if (lane < 4) {
                atomicAdd(&s_csum[cbase], csum0);
                atomicAdd(&s_csum[cbase + 1], csum1);
                atomicMax(&s_cmax[cbase], cmax0);
                atomicMax(&s_cmax[cbase + 1], cmax1);
            }
        }
#pragma unroll
        for (int ridx = 0; ridx < 4; ++ridx) {
            unsigned long long rp = (((unsigned long long)rkey[ridx]) << 32) |
                (unsigned long long)(unsigned)~(unsigned)(jbase + rjc[ridx]);
            float rs = rsum[ridx];
#pragma unroll
            for (int off = 1; off < 4; off <<= 1) {
                rs += __shfl_xor_sync(0xFFFFFFFFu, rs, off);
                unsigned long long o = __shfl_xor_sync(0xFFFFFFFFu, rp, off);
                if (o > rp) rp = o;
            }
            if (q == 0) {
                int r = mblk + (ridx >> 1) * 16 + (ridx & 1) * 8 + lr;
                atomicAdd(&s_rsum[r], rs);
                atomicMax(&s_rmax[r], rp);
            }
        }
        __syncthreads();
        if (tid < 128) {
            atomicAdd(&g_colsum[jbase + tid], s_csum[tid]);
            atomicMax(&g_colmaxp[jbase + tid], s_cmax[tid]);
            atomicAdd(&g_rowsum[ibase + tid], s_rsum[tid]);
            atomicMax(&g_rowmaxp[ibase + tid], s_rmax[tid]);
        }
    }
}

// ---------------- finalize 1: per-row/col lse, choice, lp ----------------
// key = ~bits(dist): dmin = uint_as_float(~key); lp = -dmin - log(sum exp(-dist))
__global__ void finalize1_kernel() {
    int t = blockIdx.x * blockDim.x + threadIdx.x;
    if (t >= NN) return;
    {
        unsigned long long p = g_rowmaxp[t];
        float dmin = __uint_as_float(~(unsigned)(p >> 32));
        g_choice_rows[t] = (int)(~(unsigned)(p & 0xFFFFFFFFull));
        g_lp_rows[t] = -dmin - logf(g_rowsum[t]);
    }
    {
        unsigned long long p = g_colmaxp[t];
        float dmin = __uint_as_float(~(unsigned)(p >> 32));
        g_choice_cols[t] = (int)(~(unsigned)(p & 0xFFFFFFFFull));
        g_lp_cols[t] = -dmin - logf(g_colsum[t]);
    }
}

// ---------------- finalize 2: mutual match + outputs ----------------
// out (float32): [0:M) log_probs, [M:3M) dmatches (cc, j), [3M:4M) mutual
__global__ void finalize2_kernel(float* __restrict__ out) {
    int j = blockIdx.x * blockDim.x + threadIdx.x;
    if (j >= MM) return;
    int cc = g_choice_cols[j];
    bool mut = (g_choice_rows[cc] == j);
    out[j] = mut ? (g_lp_rows[cc] + g_lp_cols[j]) : 0.f;
    out[MM + 2 * j]     = (float)cc;
    out[MM + 2 * j + 1] = (float)j;
    out[3 * MM + j] = mut ? 1.f : 0.f;
}

extern "C" void kernel_launch(void* const* d_in, const int* in_sizes, int n_in,
                              void* d_out, int out_size) {
    const float* x = (const float*)d_in[0];
    const float* y = (const float*)d_in[1];
    float* out = (float*)d_out;

    static int smem_set = 0;
    if (!smem_set) {
        cudaFuncSetAttribute(matcher_main_kernel,
                             cudaFuncAttributeMaxDynamicSharedMemorySize, SMEM_TOTAL);
        smem_set = 1;
    }

    prep_kernel<<<(2 * NN + 255) / 256, 256>>>(x, y);
    dim3 grid(NTILE, NTILE);
    matcher_main_kernel<<<grid, 256, SMEM_TOTAL>>>(x, y);
    finalize1_kernel<<<(NN + 255) / 256, 256>>>();
    finalize2_kernel<<<(MM + 255) / 256, 256>>>(out);
}